// round 4
// baseline (speedup 1.0000x reference)
#include <cuda_runtime.h>
#include <stdint.h>

#define B_USERS     4096
#define D_DIM       64
#define NNZ_CNT     204800
#define N_PAIRS     1048576
#define NUM_ITEMS_C 100000
#define REG_ROWS    (NUM_ITEMS_C + B_USERS + 1)

// Scratch (no cudaMalloc allowed)
__device__ float         g_hidden[B_USERS * D_DIM];
__device__ unsigned char g_mask[NUM_ITEMS_C];

// ---------------- Threefry-2x32 (JAX partitionable path) ----------------
__device__ __forceinline__ uint32_t rotl32(uint32_t x, int r) {
    return (x << r) | (x >> (32 - r));
}

__device__ __forceinline__ uint32_t threefry_bits(uint32_t ctr_lo) {
    const uint32_t ks0 = 0u, ks1 = 42u;
    const uint32_t ks2 = ks0 ^ ks1 ^ 0x1BD11BDAu;
    uint32_t x0 = 0u  + ks0;
    uint32_t x1 = ctr_lo + ks1;

    x0 += x1; x1 = rotl32(x1, 13); x1 ^= x0;
    x0 += x1; x1 = rotl32(x1, 15); x1 ^= x0;
    x0 += x1; x1 = rotl32(x1, 26); x1 ^= x0;
    x0 += x1; x1 = rotl32(x1,  6); x1 ^= x0;
    x0 += ks1; x1 += ks2 + 1u;
    x0 += x1; x1 = rotl32(x1, 17); x1 ^= x0;
    x0 += x1; x1 = rotl32(x1, 29); x1 ^= x0;
    x0 += x1; x1 = rotl32(x1, 16); x1 ^= x0;
    x0 += x1; x1 = rotl32(x1, 24); x1 ^= x0;
    x0 += ks2; x1 += ks0 + 2u;
    x0 += x1; x1 = rotl32(x1, 13); x1 ^= x0;
    x0 += x1; x1 = rotl32(x1, 15); x1 ^= x0;
    x0 += x1; x1 = rotl32(x1, 26); x1 ^= x0;
    x0 += x1; x1 = rotl32(x1,  6); x1 ^= x0;
    x0 += ks0; x1 += ks1 + 3u;
    x0 += x1; x1 = rotl32(x1, 17); x1 ^= x0;
    x0 += x1; x1 = rotl32(x1, 29); x1 ^= x0;
    x0 += x1; x1 = rotl32(x1, 16); x1 ^= x0;
    x0 += x1; x1 = rotl32(x1, 24); x1 ^= x0;
    x0 += ks1; x1 += ks2 + 4u;
    x0 += x1; x1 = rotl32(x1, 13); x1 ^= x0;
    x0 += x1; x1 = rotl32(x1, 15); x1 ^= x0;
    x0 += x1; x1 = rotl32(x1, 26); x1 ^= x0;
    x0 += x1; x1 = rotl32(x1,  6); x1 ^= x0;
    x0 += ks2; x1 += ks0 + 5u;

    return x0 ^ x1;
}

// ---------------- Stream A (critical path) ----------------

// hidden = user_emb[uid] + en_offset  (float4 lanes; replaces zero-init)
__global__ void k_init_hidden(const int* __restrict__ user_ids,
                              const float* __restrict__ user_emb,
                              const float* __restrict__ en_offset) {
    int idx = blockIdx.x * blockDim.x + threadIdx.x;   // exact: B*D/4 threads
    int b  = idx >> 4;
    int d4 = idx & 15;
    float4 u = __ldg((const float4*)user_emb + (size_t)__ldg(user_ids + b) * 16 + d4);
    float4 o = __ldg((const float4*)en_offset + d4);
    ((float4*)g_hidden)[idx] = make_float4(u.x + o.x, u.y + o.y, u.z + o.z, u.w + o.w);
}

// 16 lanes per nnz; keep bit computed once (lane 0 of each 16-group), broadcast.
__global__ void k_scatter(const int* __restrict__ sp_row,
                          const int* __restrict__ sp_col,
                          const float* __restrict__ en_emb) {
    int t    = blockIdx.x * blockDim.x + threadIdx.x;
    int i    = t >> 4;
    int lane = t & 15;
    int wl   = threadIdx.x & 31;

    uint32_t keep = 0;
    if (lane == 0) {
        uint32_t bits = threefry_bits((uint32_t)i);
        float u = __uint_as_float((bits >> 9) | 0x3f800000u) - 1.0f;
        keep = (u < 0.8f) ? 1u : 0u;
    }
    keep = __shfl_sync(0xffffffffu, keep, wl & 16, 32);
    if (!keep) return;

    int row = __ldg(sp_row + i);
    int col = __ldg(sp_col + i);
    float4 e = __ldg((const float4*)en_emb + (size_t)col * 16 + lane);
    float4 v = make_float4(1.25f * e.x, 1.25f * e.y, 1.25f * e.z, 1.25f * e.w);
    atomicAdd((float4*)(g_hidden + (size_t)row * 64 + lane * 4), v);
}

// tanh in place, float4
__global__ void k_tanh() {
    int idx = blockIdx.x * blockDim.x + threadIdx.x;   // exact: B*D/4 threads
    float4 v = ((const float4*)g_hidden)[idx];
    ((float4*)g_hidden)[idx] = make_float4(tanhf(v.x), tanhf(v.y), tanhf(v.z), tanhf(v.w));
}

__device__ __forceinline__ float dot4(float4 a, float4 b) {
    return a.x * b.x + a.y * b.y + a.z * b.z + a.w * b.w;
}

// 8 lanes per pair, 4 pairs per warp; full-128B-line loads, MLP=4/thread.
__global__ void __launch_bounds__(256) k_decode(
        const int* __restrict__ bat_idx,
        const int* __restrict__ bat_items,
        const float* __restrict__ de_emb,
        const float* __restrict__ de_bias,
        float* __restrict__ out) {
    int t = blockIdx.x * blockDim.x + threadIdx.x;
    int n = t >> 3;
    int l = t & 7;

    int b  = __ldg(bat_idx + n);
    int it = __ldg(bat_items + n);

    const float4* hp = (const float4*)g_hidden + (size_t)b  * 16;
    const float4* ep = (const float4*)de_emb   + (size_t)it * 16;

    float4 h0 = hp[l],         h1 = hp[l + 8];
    float4 e0 = __ldg(ep + l), e1 = __ldg(ep + l + 8);

    float p = dot4(h0, e0) + dot4(h1, e1);
    p += __shfl_xor_sync(0xffffffffu, p, 1);
    p += __shfl_xor_sync(0xffffffffu, p, 2);
    p += __shfl_xor_sync(0xffffffffu, p, 4);

    if (l == 0) out[n] = p + __ldg(de_bias + it);
}

// ---------------- Stream B (off critical path) ----------------

__global__ void k_zero_mask(float* reg_out) {
    int idx = blockIdx.x * blockDim.x + threadIdx.x;
    if (idx * 4 < NUM_ITEMS_C) ((uint32_t*)g_mask)[idx] = 0;
    if (idx == 0 && reg_out) *reg_out = 0.0f;
}

__global__ void k_item_mask(const int* __restrict__ bat_items) {
    int n = blockIdx.x * blockDim.x + threadIdx.x;   // exact: N_PAIRS threads
    g_mask[__ldg(bat_items + n)] = 1;
}

__global__ void k_reg(const float* __restrict__ en_emb,
                      const float* __restrict__ en_offset,
                      const float* __restrict__ de_emb,
                      const float* __restrict__ de_bias,
                      const float* __restrict__ user_emb,
                      const int*   __restrict__ user_ids,
                      float* __restrict__ reg_out) {
    __shared__ float bacc;
    if (threadIdx.x == 0) bacc = 0.0f;
    __syncthreads();

    int t    = blockIdx.x * blockDim.x + threadIdx.x;
    int r    = t >> 4;
    int lane = t & 15;
    float c = 0.0f;

    if (r < NUM_ITEMS_C) {
        if (g_mask[r]) {
            float4 e = __ldg((const float4*)en_emb + (size_t)r * 16 + lane);
            float4 d = __ldg((const float4*)de_emb + (size_t)r * 16 + lane);
            c = e.x * e.x + e.y * e.y + e.z * e.z + e.w * e.w
              + d.x * d.x + d.y * d.y + d.z * d.z + d.w * d.w;
            if (lane == 0) { float bb = __ldg(de_bias + r); c += bb * bb; }
        }
    } else if (r < NUM_ITEMS_C + B_USERS) {
        int b = r - NUM_ITEMS_C;
        float4 u = __ldg((const float4*)user_emb + (size_t)__ldg(user_ids + b) * 16 + lane);
        c = u.x * u.x + u.y * u.y + u.z * u.z + u.w * u.w;
    } else if (r == NUM_ITEMS_C + B_USERS) {
        float4 o = __ldg((const float4*)en_offset + lane);
        c = o.x * o.x + o.y * o.y + o.z * o.z + o.w * o.w;
    }
    c += __shfl_xor_sync(0xffffffffu, c, 1);
    c += __shfl_xor_sync(0xffffffffu, c, 2);
    c += __shfl_xor_sync(0xffffffffu, c, 4);
    c += __shfl_xor_sync(0xffffffffu, c, 8);
    if (lane == 0 && c != 0.0f) atomicAdd(&bacc, c);
    __syncthreads();
    if (threadIdx.x == 0 && bacc != 0.0f) atomicAdd(reg_out, 0.5f * bacc);
}

extern "C" void kernel_launch(void* const* d_in, const int* in_sizes, int n_in,
                              void* d_out, int out_size) {
    const int*   user_ids  = (const int*)d_in[0];
    const int*   bat_idx   = (const int*)d_in[1];
    const int*   sp_row    = (const int*)d_in[2];
    const int*   sp_col    = (const int*)d_in[3];
    const int*   bat_items = (const int*)d_in[4];
    const float* en_emb    = (const float*)d_in[5];
    const float* en_offset = (const float*)d_in[6];
    const float* de_emb    = (const float*)d_in[7];
    const float* de_bias   = (const float*)d_in[8];
    const float* user_emb  = (const float*)d_in[9];
    float* out = (float*)d_out;
    float* reg_out = (out_size > N_PAIRS) ? (out + N_PAIRS) : nullptr;

    // Side stream + fork/join events (created once, outside capture on first call)
    static cudaStream_t sB = nullptr;
    static cudaEvent_t evFork = nullptr, evJoin = nullptr;
    if (!sB) {
        cudaStreamCreateWithFlags(&sB, cudaStreamNonBlocking);
        cudaEventCreateWithFlags(&evFork, cudaEventDisableTiming);
        cudaEventCreateWithFlags(&evJoin, cudaEventDisableTiming);
    }

    // Fork side branch from the (captured) origin stream
    cudaEventRecord(evFork, 0);
    cudaStreamWaitEvent(sB, evFork, 0);

    // ---- Stream B: item mask + reg loss (independent of hidden/decode) ----
    if (reg_out) {
        k_zero_mask<<<(NUM_ITEMS_C / 4 + 255) / 256, 256, 0, sB>>>(reg_out);
        k_item_mask<<<N_PAIRS / 256, 256, 0, sB>>>(bat_items);
        k_reg<<<(REG_ROWS * 16 + 255) / 256, 256, 0, sB>>>(
            en_emb, en_offset, de_emb, de_bias, user_emb, user_ids, reg_out);
    }
    cudaEventRecord(evJoin, sB);

    // ---- Stream A: critical path ----
    k_init_hidden<<<(B_USERS * D_DIM / 4) / 256, 256>>>(user_ids, user_emb, en_offset);
    k_scatter<<<(NNZ_CNT * 16) / 256, 256>>>(sp_row, sp_col, en_emb);
    k_tanh<<<(B_USERS * D_DIM / 4) / 256, 256>>>();
    k_decode<<<(N_PAIRS * 8) / 256, 256>>>(bat_idx, bat_items, de_emb, de_bias, out);

    // Join side branch back into the origin stream
    cudaStreamWaitEvent(0, evJoin, 0);
}

// round 6
// speedup vs baseline: 1.0662x; 1.0662x over previous
#include <cuda_runtime.h>
#include <cuda_fp16.h>
#include <stdint.h>

#define B_USERS     4096
#define D_DIM       64
#define NNZ_CNT     204800
#define N_PAIRS     1048576
#define NUM_ITEMS_C 100000
#define REG_ROWS    (NUM_ITEMS_C + B_USERS + 1)

// Scratch (no cudaMalloc allowed)
__device__ float         g_hidden[B_USERS * D_DIM];
__device__ __half        g_hidden_h[B_USERS * D_DIM];
__device__ __half        g_de_h[NUM_ITEMS_C * D_DIM];
__device__ unsigned char g_mask[NUM_ITEMS_C];

// ---------------- Threefry-2x32 (JAX partitionable path) ----------------
__device__ __forceinline__ uint32_t rotl32(uint32_t x, int r) {
    return (x << r) | (x >> (32 - r));
}

__device__ __forceinline__ uint32_t threefry_bits(uint32_t ctr_lo) {
    const uint32_t ks0 = 0u, ks1 = 42u;
    const uint32_t ks2 = ks0 ^ ks1 ^ 0x1BD11BDAu;
    uint32_t x0 = 0u  + ks0;
    uint32_t x1 = ctr_lo + ks1;

    x0 += x1; x1 = rotl32(x1, 13); x1 ^= x0;
    x0 += x1; x1 = rotl32(x1, 15); x1 ^= x0;
    x0 += x1; x1 = rotl32(x1, 26); x1 ^= x0;
    x0 += x1; x1 = rotl32(x1,  6); x1 ^= x0;
    x0 += ks1; x1 += ks2 + 1u;
    x0 += x1; x1 = rotl32(x1, 17); x1 ^= x0;
    x0 += x1; x1 = rotl32(x1, 29); x1 ^= x0;
    x0 += x1; x1 = rotl32(x1, 16); x1 ^= x0;
    x0 += x1; x1 = rotl32(x1, 24); x1 ^= x0;
    x0 += ks2; x1 += ks0 + 2u;
    x0 += x1; x1 = rotl32(x1, 13); x1 ^= x0;
    x0 += x1; x1 = rotl32(x1, 15); x1 ^= x0;
    x0 += x1; x1 = rotl32(x1, 26); x1 ^= x0;
    x0 += x1; x1 = rotl32(x1,  6); x1 ^= x0;
    x0 += ks0; x1 += ks1 + 3u;
    x0 += x1; x1 = rotl32(x1, 17); x1 ^= x0;
    x0 += x1; x1 = rotl32(x1, 29); x1 ^= x0;
    x0 += x1; x1 = rotl32(x1, 16); x1 ^= x0;
    x0 += x1; x1 = rotl32(x1, 24); x1 ^= x0;
    x0 += ks1; x1 += ks2 + 4u;
    x0 += x1; x1 = rotl32(x1, 13); x1 ^= x0;
    x0 += x1; x1 = rotl32(x1, 15); x1 ^= x0;
    x0 += x1; x1 = rotl32(x1, 26); x1 ^= x0;
    x0 += x1; x1 = rotl32(x1,  6); x1 ^= x0;
    x0 += ks2; x1 += ks0 + 5u;

    return x0 ^ x1;
}

// ---------------- fp16 pack helpers ----------------
__device__ __forceinline__ uint32_t pack_h2(float a, float b) {
    __half2 h = __floats2half2_rn(a, b);
    return *reinterpret_cast<uint32_t*>(&h);
}

__device__ __forceinline__ uint4 pack_8(float4 a, float4 b) {
    return make_uint4(pack_h2(a.x, a.y), pack_h2(a.z, a.w),
                      pack_h2(b.x, b.y), pack_h2(b.z, b.w));
}

// ---------------- Kernels (single stream, program order) ----------------

// Convert de_emb fp32 -> fp16 (8 elems/thread); also zero g_mask and reg_out.
__global__ void k_convert_de(const float* __restrict__ de_emb, float* reg_out) {
    int idx = blockIdx.x * blockDim.x + threadIdx.x;
    if (idx < NUM_ITEMS_C * D_DIM / 8) {
        float4 a = __ldg((const float4*)de_emb + idx * 2);
        float4 b = __ldg((const float4*)de_emb + idx * 2 + 1);
        ((uint4*)g_de_h)[idx] = pack_8(a, b);
    }
    if (idx * 4 < NUM_ITEMS_C) ((uint32_t*)g_mask)[idx] = 0;   // 25000 words
    if (idx == 0 && reg_out) *reg_out = 0.0f;
}

// hidden = user_emb[uid] + en_offset
__global__ void k_init_hidden(const int* __restrict__ user_ids,
                              const float* __restrict__ user_emb,
                              const float* __restrict__ en_offset) {
    int idx = blockIdx.x * blockDim.x + threadIdx.x;   // exact: B*D/4 threads
    int b  = idx >> 4;
    int d4 = idx & 15;
    float4 u = __ldg((const float4*)user_emb + (size_t)__ldg(user_ids + b) * 16 + d4);
    float4 o = __ldg((const float4*)en_offset + d4);
    ((float4*)g_hidden)[idx] = make_float4(u.x + o.x, u.y + o.y, u.z + o.z, u.w + o.w);
}

// 16 lanes per nnz; keep bit computed once per nnz, broadcast via shuffle.
__global__ void k_scatter(const int* __restrict__ sp_row,
                          const int* __restrict__ sp_col,
                          const float* __restrict__ en_emb) {
    int t    = blockIdx.x * blockDim.x + threadIdx.x;
    int i    = t >> 4;
    int lane = t & 15;
    int wl   = threadIdx.x & 31;

    uint32_t keep = 0;
    if (lane == 0) {
        uint32_t bits = threefry_bits((uint32_t)i);
        float u = __uint_as_float((bits >> 9) | 0x3f800000u) - 1.0f;
        keep = (u < 0.8f) ? 1u : 0u;
    }
    keep = __shfl_sync(0xffffffffu, keep, wl & 16, 32);
    if (!keep) return;

    int row = __ldg(sp_row + i);
    int col = __ldg(sp_col + i);
    float4 e = __ldg((const float4*)en_emb + (size_t)col * 16 + lane);
    float4 v = make_float4(1.25f * e.x, 1.25f * e.y, 1.25f * e.z, 1.25f * e.w);
    atomicAdd((float4*)(g_hidden + (size_t)row * 64 + lane * 4), v);
}

// tanh in place + fp16 copy (8 elems/thread)
__global__ void k_tanh() {
    int idx = blockIdx.x * blockDim.x + threadIdx.x;   // exact: B*D/8 = 32768
    float4 a = ((const float4*)g_hidden)[idx * 2];
    float4 b = ((const float4*)g_hidden)[idx * 2 + 1];
    a = make_float4(tanhf(a.x), tanhf(a.y), tanhf(a.z), tanhf(a.w));
    b = make_float4(tanhf(b.x), tanhf(b.y), tanhf(b.z), tanhf(b.w));
    ((uint4*)g_hidden_h)[idx] = pack_8(a, b);
}

__global__ void k_item_mask(const int* __restrict__ bat_items) {
    int n = blockIdx.x * blockDim.x + threadIdx.x;   // exact: N_PAIRS threads
    g_mask[__ldg(bat_items + n)] = 1;
}

__device__ __forceinline__ float dot8h(uint4 hv, uint4 ev) {
    float acc = 0.0f;
    const uint32_t* hw = (const uint32_t*)&hv;
    const uint32_t* ew = (const uint32_t*)&ev;
#pragma unroll
    for (int i = 0; i < 4; i++) {
        float2 f = __half22float2(*(const __half2*)&hw[i]);
        float2 g = __half22float2(*(const __half2*)&ew[i]);
        acc += f.x * g.x + f.y * g.y;
    }
    return acc;
}

// fp16 decode: 8 lanes per group, each group handles 2 consecutive pairs.
// Row = 64 halves = 128B = exactly one line; lane l loads uint4 l of each row.
// Per thread: 4 independent uint4 loads (MLP 4) + 2 int2 index loads.
__global__ void __launch_bounds__(256) k_decode(
        const int* __restrict__ bat_idx,
        const int* __restrict__ bat_items,
        const float* __restrict__ de_bias,
        float* __restrict__ out) {
    int t = blockIdx.x * blockDim.x + threadIdx.x;
    int g = t >> 3;             // group handles pairs 2g, 2g+1  (N/2 groups)
    int l = t & 7;

    int2 bb = __ldg((const int2*)bat_idx + g);
    int2 ii = __ldg((const int2*)bat_items + g);

    const uint4* h0p = (const uint4*)g_hidden_h + (size_t)bb.x * 8;
    const uint4* h1p = (const uint4*)g_hidden_h + (size_t)bb.y * 8;
    const uint4* e0p = (const uint4*)g_de_h     + (size_t)ii.x * 8;
    const uint4* e1p = (const uint4*)g_de_h     + (size_t)ii.y * 8;

    uint4 h0 = h0p[l], h1 = h1p[l];
    uint4 e0 = e0p[l], e1 = e1p[l];

    float p0 = dot8h(h0, e0);
    float p1 = dot8h(h1, e1);
    p0 += __shfl_xor_sync(0xffffffffu, p0, 1);
    p1 += __shfl_xor_sync(0xffffffffu, p1, 1);
    p0 += __shfl_xor_sync(0xffffffffu, p0, 2);
    p1 += __shfl_xor_sync(0xffffffffu, p1, 2);
    p0 += __shfl_xor_sync(0xffffffffu, p0, 4);
    p1 += __shfl_xor_sync(0xffffffffu, p1, 4);

    if (l == 0) {
        float b0 = __ldg(de_bias + ii.x);
        float b1 = __ldg(de_bias + ii.y);
        ((float2*)out)[g] = make_float2(p0 + b0, p1 + b1);
    }
}

// 16 threads per row over items + user rows + one en_offset row.
__global__ void k_reg(const float* __restrict__ en_emb,
                      const float* __restrict__ en_offset,
                      const float* __restrict__ de_emb,
                      const float* __restrict__ de_bias,
                      const float* __restrict__ user_emb,
                      const int*   __restrict__ user_ids,
                      float* __restrict__ reg_out) {
    __shared__ float bacc;
    if (threadIdx.x == 0) bacc = 0.0f;
    __syncthreads();

    int t    = blockIdx.x * blockDim.x + threadIdx.x;
    int r    = t >> 4;
    int lane = t & 15;
    float c = 0.0f;

    if (r < NUM_ITEMS_C) {
        if (g_mask[r]) {
            float4 e = __ldg((const float4*)en_emb + (size_t)r * 16 + lane);
            float4 d = __ldg((const float4*)de_emb + (size_t)r * 16 + lane);
            c = e.x * e.x + e.y * e.y + e.z * e.z + e.w * e.w
              + d.x * d.x + d.y * d.y + d.z * d.z + d.w * d.w;
            if (lane == 0) { float bb = __ldg(de_bias + r); c += bb * bb; }
        }
    } else if (r < NUM_ITEMS_C + B_USERS) {
        int b = r - NUM_ITEMS_C;
        float4 u = __ldg((const float4*)user_emb + (size_t)__ldg(user_ids + b) * 16 + lane);
        c = u.x * u.x + u.y * u.y + u.z * u.z + u.w * u.w;
    } else if (r == NUM_ITEMS_C + B_USERS) {
        float4 o = __ldg((const float4*)en_offset + lane);
        c = o.x * o.x + o.y * o.y + o.z * o.z + o.w * o.w;
    }
    c += __shfl_xor_sync(0xffffffffu, c, 1);
    c += __shfl_xor_sync(0xffffffffu, c, 2);
    c += __shfl_xor_sync(0xffffffffu, c, 4);
    c += __shfl_xor_sync(0xffffffffu, c, 8);
    if (lane == 0 && c != 0.0f) atomicAdd(&bacc, c);
    __syncthreads();
    if (threadIdx.x == 0 && bacc != 0.0f) atomicAdd(reg_out, 0.5f * bacc);
}

extern "C" void kernel_launch(void* const* d_in, const int* in_sizes, int n_in,
                              void* d_out, int out_size) {
    const int*   user_ids  = (const int*)d_in[0];
    const int*   bat_idx   = (const int*)d_in[1];
    const int*   sp_row    = (const int*)d_in[2];
    const int*   sp_col    = (const int*)d_in[3];
    const int*   bat_items = (const int*)d_in[4];
    const float* en_emb    = (const float*)d_in[5];
    const float* en_offset = (const float*)d_in[6];
    const float* de_emb    = (const float*)d_in[7];
    const float* de_bias   = (const float*)d_in[8];
    const float* user_emb  = (const float*)d_in[9];
    float* out = (float*)d_out;
    float* reg_out = (out_size > N_PAIRS) ? (out + N_PAIRS) : nullptr;

    k_convert_de<<<(NUM_ITEMS_C * D_DIM / 8 + 255) / 256, 256>>>(de_emb, reg_out);
    k_init_hidden<<<(B_USERS * D_DIM / 4) / 256, 256>>>(user_ids, user_emb, en_offset);
    k_scatter<<<(NNZ_CNT * 16) / 256, 256>>>(sp_row, sp_col, en_emb);
    k_tanh<<<(B_USERS * D_DIM / 8) / 256, 256>>>();
    k_decode<<<(N_PAIRS * 4) / 256, 256>>>(bat_idx, bat_items, de_bias, out);
    if (reg_out) {
        k_item_mask<<<N_PAIRS / 256, 256>>>(bat_items);
        k_reg<<<(REG_ROWS * 16 + 255) / 256, 256>>>(en_emb, en_offset, de_emb,
                                                    de_bias, user_emb, user_ids, reg_out);
    }
}

// round 7
// speedup vs baseline: 1.2282x; 1.1520x over previous
#include <cuda_runtime.h>
#include <cuda_fp16.h>
#include <stdint.h>

#define B_USERS     4096
#define D_DIM       64
#define NNZ_CNT     204800
#define N_PAIRS     1048576
#define NUM_ITEMS_C 100000
#define REG_ROWS    (NUM_ITEMS_C + B_USERS + 1)

#define DECODE_BLOCKS (N_PAIRS * 2 / 256)                 // 8192 (2M threads, 4 pairs / 8 lanes)
#define REG_BLOCKS    ((REG_ROWS * 16 + 255) / 256)       // 6507
#define PRE_THREADS   (NUM_ITEMS_C * D_DIM / 8)           // 800000

// Scratch (no cudaMalloc allowed)
__device__ float         g_hidden[B_USERS * D_DIM];
__device__ __half        g_hidden_h[B_USERS * D_DIM];
__device__ __half        g_de_h[NUM_ITEMS_C * D_DIM];
__device__ unsigned char g_mask[NUM_ITEMS_C];

// ---------------- Threefry-2x32 (JAX partitionable path) ----------------
__device__ __forceinline__ uint32_t rotl32(uint32_t x, int r) {
    return (x << r) | (x >> (32 - r));
}

__device__ __forceinline__ uint32_t threefry_bits(uint32_t ctr_lo) {
    const uint32_t ks0 = 0u, ks1 = 42u;
    const uint32_t ks2 = ks0 ^ ks1 ^ 0x1BD11BDAu;
    uint32_t x0 = 0u  + ks0;
    uint32_t x1 = ctr_lo + ks1;

    x0 += x1; x1 = rotl32(x1, 13); x1 ^= x0;
    x0 += x1; x1 = rotl32(x1, 15); x1 ^= x0;
    x0 += x1; x1 = rotl32(x1, 26); x1 ^= x0;
    x0 += x1; x1 = rotl32(x1,  6); x1 ^= x0;
    x0 += ks1; x1 += ks2 + 1u;
    x0 += x1; x1 = rotl32(x1, 17); x1 ^= x0;
    x0 += x1; x1 = rotl32(x1, 29); x1 ^= x0;
    x0 += x1; x1 = rotl32(x1, 16); x1 ^= x0;
    x0 += x1; x1 = rotl32(x1, 24); x1 ^= x0;
    x0 += ks2; x1 += ks0 + 2u;
    x0 += x1; x1 = rotl32(x1, 13); x1 ^= x0;
    x0 += x1; x1 = rotl32(x1, 15); x1 ^= x0;
    x0 += x1; x1 = rotl32(x1, 26); x1 ^= x0;
    x0 += x1; x1 = rotl32(x1,  6); x1 ^= x0;
    x0 += ks0; x1 += ks1 + 3u;
    x0 += x1; x1 = rotl32(x1, 17); x1 ^= x0;
    x0 += x1; x1 = rotl32(x1, 29); x1 ^= x0;
    x0 += x1; x1 = rotl32(x1, 16); x1 ^= x0;
    x0 += x1; x1 = rotl32(x1, 24); x1 ^= x0;
    x0 += ks1; x1 += ks2 + 4u;
    x0 += x1; x1 = rotl32(x1, 13); x1 ^= x0;
    x0 += x1; x1 = rotl32(x1, 15); x1 ^= x0;
    x0 += x1; x1 = rotl32(x1, 26); x1 ^= x0;
    x0 += x1; x1 = rotl32(x1,  6); x1 ^= x0;
    x0 += ks2; x1 += ks0 + 5u;

    return x0 ^ x1;
}

// ---------------- fp16 pack helpers ----------------
__device__ __forceinline__ uint32_t pack_h2(float a, float b) {
    __half2 h = __floats2half2_rn(a, b);
    return *reinterpret_cast<uint32_t*>(&h);
}
__device__ __forceinline__ uint4 pack_8(float4 a, float4 b) {
    return make_uint4(pack_h2(a.x, a.y), pack_h2(a.z, a.w),
                      pack_h2(b.x, b.y), pack_h2(b.z, b.w));
}

// ---------------- K1: fused preamble ----------------
// convert de_emb -> fp16 | init hidden = user_emb[uid] + offset | zero mask | zero reg
__global__ void k_pre(const float* __restrict__ de_emb,
                      const int*   __restrict__ user_ids,
                      const float* __restrict__ user_emb,
                      const float* __restrict__ en_offset,
                      float* reg_out) {
    int idx = blockIdx.x * blockDim.x + threadIdx.x;   // exact: PRE_THREADS

    float4 a = __ldg((const float4*)de_emb + idx * 2);
    float4 b = __ldg((const float4*)de_emb + idx * 2 + 1);
    ((uint4*)g_de_h)[idx] = pack_8(a, b);

    if (idx < B_USERS * D_DIM / 4) {
        int bu = idx >> 4;
        int d4 = idx & 15;
        float4 u = __ldg((const float4*)user_emb + (size_t)__ldg(user_ids + bu) * 16 + d4);
        float4 o = __ldg((const float4*)en_offset + d4);
        ((float4*)g_hidden)[idx] = make_float4(u.x + o.x, u.y + o.y, u.z + o.z, u.w + o.w);
    }
    if (idx * 4 < NUM_ITEMS_C) ((uint32_t*)g_mask)[idx] = 0;
    if (idx == 0 && reg_out) *reg_out = 0.0f;
}

// ---------------- K2: scatter + item-mask ----------------
__global__ void k_scatter(const int* __restrict__ sp_row,
                          const int* __restrict__ sp_col,
                          const float* __restrict__ en_emb,
                          const int* __restrict__ bat_items) {
    int t    = blockIdx.x * blockDim.x + threadIdx.x;
    int i    = t >> 4;
    int lane = t & 15;
    int wl   = threadIdx.x & 31;

    // independent work before the dependency sync
    uint32_t keep = 0;
    if (lane == 0) {
        uint32_t bits = threefry_bits((uint32_t)i);
        float u = __uint_as_float((bits >> 9) | 0x3f800000u) - 1.0f;
        keep = (u < 0.8f) ? 1u : 0u;
    }
    keep = __shfl_sync(0xffffffffu, keep, wl & 16, 32);
    int item = (t < N_PAIRS) ? __ldg(bat_items + t) : -1;

    cudaGridDependencySynchronize();   // K1's g_hidden init + g_mask zero complete

    if (item >= 0) g_mask[item] = 1;
    if (!keep) return;

    int row = __ldg(sp_row + i);
    int col = __ldg(sp_col + i);
    float4 e = __ldg((const float4*)en_emb + (size_t)col * 16 + lane);
    float4 v = make_float4(1.25f * e.x, 1.25f * e.y, 1.25f * e.z, 1.25f * e.w);
    atomicAdd((float4*)(g_hidden + (size_t)row * 64 + lane * 4), v);
}

// ---------------- K3: tanh + fp16 copy ----------------
__global__ void k_tanh() {
    cudaGridDependencySynchronize();
    int idx = blockIdx.x * blockDim.x + threadIdx.x;   // exact: B*D/8 = 32768
    float4 a = ((const float4*)g_hidden)[idx * 2];
    float4 b = ((const float4*)g_hidden)[idx * 2 + 1];
    a = make_float4(tanhf(a.x), tanhf(a.y), tanhf(a.z), tanhf(a.w));
    b = make_float4(tanhf(b.x), tanhf(b.y), tanhf(b.z), tanhf(b.w));
    ((uint4*)g_hidden_h)[idx] = pack_8(a, b);
}

// ---------------- K4: decode (blocks < DECODE_BLOCKS) + reg (rest) ----------------
__device__ __forceinline__ float dot8h(uint4 hv, uint4 ev) {
    float acc = 0.0f;
    const uint32_t* hw = (const uint32_t*)&hv;
    const uint32_t* ew = (const uint32_t*)&ev;
#pragma unroll
    for (int i = 0; i < 4; i++) {
        float2 f = __half22float2(*(const __half2*)&hw[i]);
        float2 g = __half22float2(*(const __half2*)&ew[i]);
        acc += f.x * g.x + f.y * g.y;
    }
    return acc;
}

__global__ void __launch_bounds__(256) k_decode_reg(
        const int* __restrict__ bat_idx,
        const int* __restrict__ bat_items,
        const float* __restrict__ de_bias,
        const float* __restrict__ en_emb,
        const float* __restrict__ en_offset,
        const float* __restrict__ de_emb,
        const float* __restrict__ user_emb,
        const int*   __restrict__ user_ids,
        float* __restrict__ out,
        float* __restrict__ reg_out) {
    if (blockIdx.x < DECODE_BLOCKS) {
        int t = blockIdx.x * blockDim.x + threadIdx.x;
        int g = t >> 3;             // group handles pairs 4g..4g+3
        int l = t & 7;

        int4 bb = __ldg((const int4*)bat_idx + g);
        int4 ii = __ldg((const int4*)bat_items + g);
        cudaGridDependencySynchronize();   // hidden_h ready

        uint4 h0 = ((const uint4*)g_hidden_h + (size_t)bb.x * 8)[l];
        uint4 h1 = ((const uint4*)g_hidden_h + (size_t)bb.y * 8)[l];
        uint4 h2 = ((const uint4*)g_hidden_h + (size_t)bb.z * 8)[l];
        uint4 h3 = ((const uint4*)g_hidden_h + (size_t)bb.w * 8)[l];
        uint4 e0 = ((const uint4*)g_de_h + (size_t)ii.x * 8)[l];
        uint4 e1 = ((const uint4*)g_de_h + (size_t)ii.y * 8)[l];
        uint4 e2 = ((const uint4*)g_de_h + (size_t)ii.z * 8)[l];
        uint4 e3 = ((const uint4*)g_de_h + (size_t)ii.w * 8)[l];

        float p0 = dot8h(h0, e0);
        float p1 = dot8h(h1, e1);
        float p2 = dot8h(h2, e2);
        float p3 = dot8h(h3, e3);
#pragma unroll
        for (int s = 1; s <= 4; s <<= 1) {
            p0 += __shfl_xor_sync(0xffffffffu, p0, s);
            p1 += __shfl_xor_sync(0xffffffffu, p1, s);
            p2 += __shfl_xor_sync(0xffffffffu, p2, s);
            p3 += __shfl_xor_sync(0xffffffffu, p3, s);
        }
        if (l == 0) {
            float4 r = make_float4(p0 + __ldg(de_bias + ii.x),
                                   p1 + __ldg(de_bias + ii.y),
                                   p2 + __ldg(de_bias + ii.z),
                                   p3 + __ldg(de_bias + ii.w));
            ((float4*)out)[g] = r;
        }
    } else {
        cudaGridDependencySynchronize();   // g_mask (K2) complete via stream order
        __shared__ float bacc;
        if (threadIdx.x == 0) bacc = 0.0f;
        __syncthreads();

        int t    = (blockIdx.x - DECODE_BLOCKS) * blockDim.x + threadIdx.x;
        int r    = t >> 4;
        int lane = t & 15;
        float c = 0.0f;

        if (r < NUM_ITEMS_C) {
            if (g_mask[r]) {
                float4 e = __ldg((const float4*)en_emb + (size_t)r * 16 + lane);
                float4 d = __ldg((const float4*)de_emb + (size_t)r * 16 + lane);
                c = e.x * e.x + e.y * e.y + e.z * e.z + e.w * e.w
                  + d.x * d.x + d.y * d.y + d.z * d.z + d.w * d.w;
                if (lane == 0) { float bb = __ldg(de_bias + r); c += bb * bb; }
            }
        } else if (r < NUM_ITEMS_C + B_USERS) {
            int b = r - NUM_ITEMS_C;
            float4 u = __ldg((const float4*)user_emb + (size_t)__ldg(user_ids + b) * 16 + lane);
            c = u.x * u.x + u.y * u.y + u.z * u.z + u.w * u.w;
        } else if (r == NUM_ITEMS_C + B_USERS) {
            float4 o = __ldg((const float4*)en_offset + lane);
            c = o.x * o.x + o.y * o.y + o.z * o.z + o.w * o.w;
        }
        c += __shfl_xor_sync(0xffffffffu, c, 1);
        c += __shfl_xor_sync(0xffffffffu, c, 2);
        c += __shfl_xor_sync(0xffffffffu, c, 4);
        c += __shfl_xor_sync(0xffffffffu, c, 8);
        if (lane == 0 && c != 0.0f) atomicAdd(&bacc, c);
        __syncthreads();
        if (threadIdx.x == 0 && bacc != 0.0f && reg_out) atomicAdd(reg_out, 0.5f * bacc);
    }
}

// ---------------- launch ----------------
static void launch_pdl(void* fn, dim3 grid, void** args) {
    cudaLaunchConfig_t cfg = {};
    cfg.gridDim = grid;
    cfg.blockDim = dim3(256);
    cfg.dynamicSmemBytes = 0;
    cfg.stream = 0;
    cudaLaunchAttribute attr[1];
    attr[0].id = cudaLaunchAttributeProgrammaticStreamSerialization;
    attr[0].val.programmaticStreamSerializationAllowed = 1;
    cfg.attrs = attr;
    cfg.numAttrs = 1;
    cudaLaunchKernelExC(&cfg, fn, args);
}

extern "C" void kernel_launch(void* const* d_in, const int* in_sizes, int n_in,
                              void* d_out, int out_size) {
    const int*   user_ids  = (const int*)d_in[0];
    const int*   bat_idx   = (const int*)d_in[1];
    const int*   sp_row    = (const int*)d_in[2];
    const int*   sp_col    = (const int*)d_in[3];
    const int*   bat_items = (const int*)d_in[4];
    const float* en_emb    = (const float*)d_in[5];
    const float* en_offset = (const float*)d_in[6];
    const float* de_emb    = (const float*)d_in[7];
    const float* de_bias   = (const float*)d_in[8];
    const float* user_emb  = (const float*)d_in[9];
    float* out = (float*)d_out;
    float* reg_out = (out_size > N_PAIRS) ? (out + N_PAIRS) : nullptr;

    // K1 (normal launch)
    k_pre<<<PRE_THREADS / 256, 256>>>(de_emb, user_ids, user_emb, en_offset, reg_out);

    // K2..K4 PDL-chained
    {
        void* args[] = { (void*)&sp_row, (void*)&sp_col, (void*)&en_emb, (void*)&bat_items };
        launch_pdl((void*)k_scatter, dim3(NNZ_CNT * 16 / 256), args);
    }
    {
        void* args[] = {};
        launch_pdl((void*)k_tanh, dim3(B_USERS * D_DIM / 8 / 256), args);
    }
    {
        void* args[] = { (void*)&bat_idx, (void*)&bat_items, (void*)&de_bias,
                         (void*)&en_emb, (void*)&en_offset, (void*)&de_emb,
                         (void*)&user_emb, (void*)&user_ids,
                         (void*)&out, (void*)&reg_out };
        launch_pdl((void*)k_decode_reg, dim3(DECODE_BLOCKS + REG_BLOCKS), args);
    }
}

// round 8
// speedup vs baseline: 1.3907x; 1.1323x over previous
#include <cuda_runtime.h>
#include <cuda_fp16.h>
#include <stdint.h>

#define B_USERS     4096
#define D_DIM       64
#define NNZ_CNT     204800
#define N_PAIRS     1048576
#define NUM_ITEMS_C 100000

#define DECODE_BLOCKS (N_PAIRS * 2 / 256)            // 8192 (4 pairs per 8-lane group)
#define ITEM_SEG      100352                          // items segment, padded to /256
#define USER_SEG      (B_USERS * 16)                  // 65536
#define TAIL_THREADS  (ITEM_SEG + USER_SEG)           // 165888
#define TAIL_BLOCKS   (TAIL_THREADS / 256)            // 648
#define PRE_THREADS   (NUM_ITEMS_C * D_DIM / 8)       // 800000

// Scratch (no cudaMalloc allowed)
__device__ float         g_hidden[B_USERS * D_DIM];
__device__ __half        g_hidden_h[B_USERS * D_DIM];
__device__ __half        g_de_h[NUM_ITEMS_C * D_DIM];
__device__ float         g_item_reg[NUM_ITEMS_C];
__device__ unsigned char g_mask[NUM_ITEMS_C];

// ---------------- Threefry-2x32 (JAX partitionable path) ----------------
__device__ __forceinline__ uint32_t rotl32(uint32_t x, int r) {
    return (x << r) | (x >> (32 - r));
}

__device__ __forceinline__ uint32_t threefry_bits(uint32_t ctr_lo) {
    const uint32_t ks0 = 0u, ks1 = 42u;
    const uint32_t ks2 = ks0 ^ ks1 ^ 0x1BD11BDAu;
    uint32_t x0 = 0u  + ks0;
    uint32_t x1 = ctr_lo + ks1;

    x0 += x1; x1 = rotl32(x1, 13); x1 ^= x0;
    x0 += x1; x1 = rotl32(x1, 15); x1 ^= x0;
    x0 += x1; x1 = rotl32(x1, 26); x1 ^= x0;
    x0 += x1; x1 = rotl32(x1,  6); x1 ^= x0;
    x0 += ks1; x1 += ks2 + 1u;
    x0 += x1; x1 = rotl32(x1, 17); x1 ^= x0;
    x0 += x1; x1 = rotl32(x1, 29); x1 ^= x0;
    x0 += x1; x1 = rotl32(x1, 16); x1 ^= x0;
    x0 += x1; x1 = rotl32(x1, 24); x1 ^= x0;
    x0 += ks2; x1 += ks0 + 2u;
    x0 += x1; x1 = rotl32(x1, 13); x1 ^= x0;
    x0 += x1; x1 = rotl32(x1, 15); x1 ^= x0;
    x0 += x1; x1 = rotl32(x1, 26); x1 ^= x0;
    x0 += x1; x1 = rotl32(x1,  6); x1 ^= x0;
    x0 += ks0; x1 += ks1 + 3u;
    x0 += x1; x1 = rotl32(x1, 17); x1 ^= x0;
    x0 += x1; x1 = rotl32(x1, 29); x1 ^= x0;
    x0 += x1; x1 = rotl32(x1, 16); x1 ^= x0;
    x0 += x1; x1 = rotl32(x1, 24); x1 ^= x0;
    x0 += ks1; x1 += ks2 + 4u;
    x0 += x1; x1 = rotl32(x1, 13); x1 ^= x0;
    x0 += x1; x1 = rotl32(x1, 15); x1 ^= x0;
    x0 += x1; x1 = rotl32(x1, 26); x1 ^= x0;
    x0 += x1; x1 = rotl32(x1,  6); x1 ^= x0;
    x0 += ks2; x1 += ks0 + 5u;

    return x0 ^ x1;
}

// ---------------- fp16 pack helpers ----------------
__device__ __forceinline__ uint32_t pack_h2(float a, float b) {
    __half2 h = __floats2half2_rn(a, b);
    return *reinterpret_cast<uint32_t*>(&h);
}
__device__ __forceinline__ uint4 pack_8(float4 a, float4 b) {
    return make_uint4(pack_h2(a.x, a.y), pack_h2(a.z, a.w),
                      pack_h2(b.x, b.y), pack_h2(b.z, b.w));
}
__device__ __forceinline__ float sumsq4(float4 v) {
    return v.x * v.x + v.y * v.y + v.z * v.z + v.w * v.w;
}

// ---------------- K1: fused preamble ----------------
// de_emb -> fp16 | item reg norms (en+de+bias) | hidden init | zero mask/reg
__global__ void k_pre(const float* __restrict__ de_emb,
                      const float* __restrict__ en_emb,
                      const float* __restrict__ de_bias,
                      const int*   __restrict__ user_ids,
                      const float* __restrict__ user_emb,
                      const float* __restrict__ en_offset,
                      float* reg_out) {
    int idx = blockIdx.x * blockDim.x + threadIdx.x;   // exact: PRE_THREADS
    int row  = idx >> 3;      // 8 threads per item row
    int l8   = idx & 7;

    // de convert + partial norm
    float4 a = __ldg((const float4*)de_emb + idx * 2);
    float4 b = __ldg((const float4*)de_emb + idx * 2 + 1);
    ((uint4*)g_de_h)[idx] = pack_8(a, b);
    float c = sumsq4(a) + sumsq4(b);

    // en partial norm (same coords)
    float4 ea = __ldg((const float4*)en_emb + idx * 2);
    float4 eb = __ldg((const float4*)en_emb + idx * 2 + 1);
    c += sumsq4(ea) + sumsq4(eb);

    // reduce across the 8 row-threads (contiguous in warp)
    c += __shfl_xor_sync(0xffffffffu, c, 1);
    c += __shfl_xor_sync(0xffffffffu, c, 2);
    c += __shfl_xor_sync(0xffffffffu, c, 4);
    if (l8 == 0) {
        float bb = __ldg(de_bias + row);
        g_item_reg[row] = c + bb * bb;
    }

    if (idx < B_USERS * D_DIM / 4) {
        int bu = idx >> 4;
        int d4 = idx & 15;
        float4 u = __ldg((const float4*)user_emb + (size_t)__ldg(user_ids + bu) * 16 + d4);
        float4 o = __ldg((const float4*)en_offset + d4);
        ((float4*)g_hidden)[idx] = make_float4(u.x + o.x, u.y + o.y, u.z + o.z, u.w + o.w);
    }
    if (idx * 4 < NUM_ITEMS_C) ((uint32_t*)g_mask)[idx] = 0;
    if (idx == 0 && reg_out) *reg_out = 0.0f;
}

// ---------------- K2: scatter + item-mask ----------------
__global__ void k_scatter(const int* __restrict__ sp_row,
                          const int* __restrict__ sp_col,
                          const float* __restrict__ en_emb,
                          const int* __restrict__ bat_items) {
    int t    = blockIdx.x * blockDim.x + threadIdx.x;
    int i    = t >> 4;
    int lane = t & 15;
    int wl   = threadIdx.x & 31;

    uint32_t keep = 0;
    if (lane == 0) {
        uint32_t bits = threefry_bits((uint32_t)i);
        float u = __uint_as_float((bits >> 9) | 0x3f800000u) - 1.0f;
        keep = (u < 0.8f) ? 1u : 0u;
    }
    keep = __shfl_sync(0xffffffffu, keep, wl & 16, 32);
    int item = (t < N_PAIRS) ? __ldg(bat_items + t) : -1;

    cudaGridDependencySynchronize();   // K1 complete

    if (item >= 0) g_mask[item] = 1;
    if (!keep) return;

    int row = __ldg(sp_row + i);
    int col = __ldg(sp_col + i);
    float4 e = __ldg((const float4*)en_emb + (size_t)col * 16 + lane);
    float4 v = make_float4(1.25f * e.x, 1.25f * e.y, 1.25f * e.z, 1.25f * e.w);
    atomicAdd((float4*)(g_hidden + (size_t)row * 64 + lane * 4), v);
}

// ---------------- K3: tanh + fp16 copy ----------------
__global__ void k_tanh() {
    cudaGridDependencySynchronize();
    int idx = blockIdx.x * blockDim.x + threadIdx.x;   // exact: B*D/8
    float4 a = ((const float4*)g_hidden)[idx * 2];
    float4 b = ((const float4*)g_hidden)[idx * 2 + 1];
    a = make_float4(tanhf(a.x), tanhf(a.y), tanhf(a.z), tanhf(a.w));
    b = make_float4(tanhf(b.x), tanhf(b.y), tanhf(b.z), tanhf(b.w));
    ((uint4*)g_hidden_h)[idx] = pack_8(a, b);
}

// ---------------- K4: decode + tiny reg tail ----------------
__device__ __forceinline__ float dot8h(uint4 hv, uint4 ev) {
    float acc = 0.0f;
    const uint32_t* hw = (const uint32_t*)&hv;
    const uint32_t* ew = (const uint32_t*)&ev;
#pragma unroll
    for (int i = 0; i < 4; i++) {
        float2 f = __half22float2(*(const __half2*)&hw[i]);
        float2 g = __half22float2(*(const __half2*)&ew[i]);
        acc += f.x * g.x + f.y * g.y;
    }
    return acc;
}

__global__ void __launch_bounds__(256) k_decode_reg(
        const int* __restrict__ bat_idx,
        const int* __restrict__ bat_items,
        const float* __restrict__ de_bias,
        const float* __restrict__ en_offset,
        const float* __restrict__ user_emb,
        const int*   __restrict__ user_ids,
        float* __restrict__ out,
        float* __restrict__ reg_out) {
    if (blockIdx.x < DECODE_BLOCKS) {
        int t = blockIdx.x * blockDim.x + threadIdx.x;
        int g = t >> 3;             // group handles pairs 4g..4g+3
        int l = t & 7;

        int4 bb = __ldg((const int4*)bat_idx + g);
        int4 ii = __ldg((const int4*)bat_items + g);
        cudaGridDependencySynchronize();   // hidden_h ready

        uint4 h0 = ((const uint4*)g_hidden_h + (size_t)bb.x * 8)[l];
        uint4 h1 = ((const uint4*)g_hidden_h + (size_t)bb.y * 8)[l];
        uint4 h2 = ((const uint4*)g_hidden_h + (size_t)bb.z * 8)[l];
        uint4 h3 = ((const uint4*)g_hidden_h + (size_t)bb.w * 8)[l];
        uint4 e0 = ((const uint4*)g_de_h + (size_t)ii.x * 8)[l];
        uint4 e1 = ((const uint4*)g_de_h + (size_t)ii.y * 8)[l];
        uint4 e2 = ((const uint4*)g_de_h + (size_t)ii.z * 8)[l];
        uint4 e3 = ((const uint4*)g_de_h + (size_t)ii.w * 8)[l];

        float p0 = dot8h(h0, e0);
        float p1 = dot8h(h1, e1);
        float p2 = dot8h(h2, e2);
        float p3 = dot8h(h3, e3);
#pragma unroll
        for (int s = 1; s <= 4; s <<= 1) {
            p0 += __shfl_xor_sync(0xffffffffu, p0, s);
            p1 += __shfl_xor_sync(0xffffffffu, p1, s);
            p2 += __shfl_xor_sync(0xffffffffu, p2, s);
            p3 += __shfl_xor_sync(0xffffffffu, p3, s);
        }
        if (l == 0) {
            float4 r = make_float4(p0 + __ldg(de_bias + ii.x),
                                   p1 + __ldg(de_bias + ii.y),
                                   p2 + __ldg(de_bias + ii.z),
                                   p3 + __ldg(de_bias + ii.w));
            ((float4*)out)[g] = r;
        }
    } else {
        cudaGridDependencySynchronize();   // g_mask (K2), g_item_reg (K1)
        __shared__ float bacc;
        if (threadIdx.x == 0) bacc = 0.0f;
        __syncthreads();

        int t = (blockIdx.x - DECODE_BLOCKS) * blockDim.x + threadIdx.x;
        float c = 0.0f;
        if (t < NUM_ITEMS_C) {
            c = g_mask[t] ? g_item_reg[t] : 0.0f;
            if (t == 0) {
                for (int k = 0; k < D_DIM; k++) {
                    float o = __ldg(en_offset + k);
                    c += o * o;
                }
            }
        } else if (t >= ITEM_SEG && t < TAIL_THREADS) {
            int r = t - ITEM_SEG;
            int b = r >> 4, lane = r & 15;
            float4 u = __ldg((const float4*)user_emb + (size_t)__ldg(user_ids + b) * 16 + lane);
            c = sumsq4(u);
        }
        // whole-warp reduce (only total matters)
#pragma unroll
        for (int s = 1; s <= 16; s <<= 1) c += __shfl_xor_sync(0xffffffffu, c, s);
        if ((threadIdx.x & 31) == 0 && c != 0.0f) atomicAdd(&bacc, c);
        __syncthreads();
        if (threadIdx.x == 0 && bacc != 0.0f && reg_out) atomicAdd(reg_out, 0.5f * bacc);
    }
}

// ---------------- launch ----------------
static void launch_pdl(void* fn, dim3 grid, void** args) {
    cudaLaunchConfig_t cfg = {};
    cfg.gridDim = grid;
    cfg.blockDim = dim3(256);
    cfg.dynamicSmemBytes = 0;
    cfg.stream = 0;
    cudaLaunchAttribute attr[1];
    attr[0].id = cudaLaunchAttributeProgrammaticStreamSerialization;
    attr[0].val.programmaticStreamSerializationAllowed = 1;
    cfg.attrs = attr;
    cfg.numAttrs = 1;
    cudaLaunchKernelExC(&cfg, fn, args);
}

extern "C" void kernel_launch(void* const* d_in, const int* in_sizes, int n_in,
                              void* d_out, int out_size) {
    const int*   user_ids  = (const int*)d_in[0];
    const int*   bat_idx   = (const int*)d_in[1];
    const int*   sp_row    = (const int*)d_in[2];
    const int*   sp_col    = (const int*)d_in[3];
    const int*   bat_items = (const int*)d_in[4];
    const float* en_emb    = (const float*)d_in[5];
    const float* en_offset = (const float*)d_in[6];
    const float* de_emb    = (const float*)d_in[7];
    const float* de_bias   = (const float*)d_in[8];
    const float* user_emb  = (const float*)d_in[9];
    float* out = (float*)d_out;
    float* reg_out = (out_size > N_PAIRS) ? (out + N_PAIRS) : nullptr;

    k_pre<<<PRE_THREADS / 256, 256>>>(de_emb, en_emb, de_bias, user_ids,
                                      user_emb, en_offset, reg_out);
    {
        void* args[] = { (void*)&sp_row, (void*)&sp_col, (void*)&en_emb, (void*)&bat_items };
        launch_pdl((void*)k_scatter, dim3(NNZ_CNT * 16 / 256), args);
    }
    {
        void* args[] = {};
        launch_pdl((void*)k_tanh, dim3(B_USERS * D_DIM / 8 / 256), args);
    }
    {
        void* args[] = { (void*)&bat_idx, (void*)&bat_items, (void*)&de_bias,
                         (void*)&en_offset, (void*)&user_emb, (void*)&user_ids,
                         (void*)&out, (void*)&reg_out };
        launch_pdl((void*)k_decode_reg, dim3(DECODE_BLOCKS + TAIL_BLOCKS), args);
    }
}